// round 1
// baseline (speedup 1.0000x reference)
#include <cuda_runtime.h>
#include <math.h>

#define BATCH   2
#define SEQ     2048
#define NEMB    2048
#define NHEAD   16
#define HD      128
#define QKV_COLS 2304          // (16+2)*128
#define ROWS    (BATCH*SEQ)    // 4096

// Scratch (no cudaMalloc allowed)
__device__ float g_qkv[ROWS * QKV_COLS];   // ~37.7 MB
__device__ float g_att[ROWS * NEMB];       // ~33.5 MB

// ---------------------------------------------------------------------------
// SGEMM: C[M,N] = A[M,K] @ B[K,N], row-major. Requires M%128==0, N%128==0, K%8==0.
// 128x128 block tile, 8x8 per thread, BK=8, 256 threads.
// ---------------------------------------------------------------------------
__global__ __launch_bounds__(256) void sgemm_kernel(const float* __restrict__ A,
                                                    const float* __restrict__ B,
                                                    float* __restrict__ C,
                                                    int M, int N, int K) {
    __shared__ float As[8][128];
    __shared__ float Bs[8][128];
    int tid = threadIdx.x;
    int tx = tid & 15, ty = tid >> 4;
    float acc[8][8] = {};
    const float* Ab = A + (size_t)blockIdx.y * 128 * K;
    const float* Bb = B + (size_t)blockIdx.x * 128;
    int aRow = tid >> 1, aCol = (tid & 1) * 4;
    int bRow = tid >> 5, bCol = (tid & 31) * 4;
    for (int k0 = 0; k0 < K; k0 += 8) {
        float4 av = *(const float4*)(Ab + (size_t)aRow * K + k0 + aCol);
        As[aCol+0][aRow] = av.x; As[aCol+1][aRow] = av.y;
        As[aCol+2][aRow] = av.z; As[aCol+3][aRow] = av.w;
        *(float4*)&Bs[bRow][bCol] = *(const float4*)(Bb + (size_t)(k0 + bRow) * N + bCol);
        __syncthreads();
        #pragma unroll
        for (int k = 0; k < 8; k++) {
            float ar[8], br[8];
            *(float4*)&ar[0] = *(const float4*)&As[k][ty*8];
            *(float4*)&ar[4] = *(const float4*)&As[k][ty*8+4];
            *(float4*)&br[0] = *(const float4*)&Bs[k][tx*8];
            *(float4*)&br[4] = *(const float4*)&Bs[k][tx*8+4];
            #pragma unroll
            for (int i = 0; i < 8; i++)
                #pragma unroll
                for (int j = 0; j < 8; j++)
                    acc[i][j] += ar[i] * br[j];
        }
        __syncthreads();
    }
    #pragma unroll
    for (int i = 0; i < 8; i++) {
        float* Cr = C + (size_t)(blockIdx.y*128 + ty*8 + i) * N + blockIdx.x*128 + tx*8;
        *(float4*)(Cr)     = make_float4(acc[i][0], acc[i][1], acc[i][2], acc[i][3]);
        *(float4*)(Cr + 4) = make_float4(acc[i][4], acc[i][5], acc[i][6], acc[i][7]);
    }
}

// ---------------------------------------------------------------------------
// RoPE in place on q (heads 0..15) and k (offset 2048) inside g_qkv.
// Each thread handles one (row, head, pair i) -> elements i and i+64.
// ---------------------------------------------------------------------------
__global__ void rope_kernel(float* __restrict__ qkv) {
    const int total = ROWS * 17 * 64;
    int idx = blockIdx.x * blockDim.x + threadIdx.x;
    if (idx >= total) return;
    int i    = idx & 63;
    int head = (idx >> 6) % 17;
    int row  = idx / (17 * 64);
    int t    = row & (SEQ - 1);
    int off  = (head < 16) ? head * HD : 2048;
    float* p = qkv + (size_t)row * QKV_COLS + off;
    // freq = 10000^(-(4i+1)/128)
    float freq = expf(-(4.0f * (float)i + 1.0f) * (9.210340371976184f / 128.0f));
    float ang = (float)t * freq;
    float c = cosf(ang), s = sinf(ang);
    float x1 = p[i], x2 = p[i + 64];
    p[i]      = x1 * c - x2 * s;
    p[i + 64] = x2 * c + x1 * s;
}

// ---------------------------------------------------------------------------
// Flash attention (non-causal), fp32. Block = (q-tile of 64, head, batch),
// 256 threads. K/V shared by all 16 heads (MQA) but loaded per block (round 0).
// ---------------------------------------------------------------------------
#define BQ 64
#define BKT 64
#define TS 132   // padded row stride for 128-wide tiles
#define SS 68    // padded row stride for 64-wide score tile

#define ATTN_SMEM_FLOATS (4*BQ*TS + BQ*SS + 3*BQ)
#define ATTN_SMEM_BYTES  (ATTN_SMEM_FLOATS * 4)

__global__ __launch_bounds__(256) void attn_kernel(const float* __restrict__ qkv,
                                                   float* __restrict__ out) {
    const int qt  = blockIdx.x;   // 0..31
    const int h   = blockIdx.y;   // 0..15
    const int b   = blockIdx.z;   // 0..1
    const int tid = threadIdx.x;

    extern __shared__ float sm[];
    float* Qs   = sm;
    float* Ks   = Qs + BQ*TS;
    float* Vs   = Ks + BKT*TS;
    float* Os   = Vs + BKT*TS;
    float* Ss   = Os + BQ*TS;
    float* mrow = Ss + BQ*SS;
    float* lrow = mrow + BQ;
    float* crow = lrow + BQ;

    const float scale = 0.08838834764831845f;   // 1/sqrt(128)
    const size_t base = (size_t)b * SEQ * QKV_COLS;

    // Load Q tile and zero O
    {
        int r  = tid >> 2;
        int c0 = (tid & 3) * 32;
        const float* src = qkv + base + (size_t)(qt*BQ + r) * QKV_COLS + h*HD + c0;
        #pragma unroll
        for (int j = 0; j < 8; j++) {
            *(float4*)&Qs[r*TS + c0 + j*4] = *(const float4*)(src + j*4);
            *(float4*)&Os[r*TS + c0 + j*4] = make_float4(0.f, 0.f, 0.f, 0.f);
        }
    }
    if (tid < BQ) { mrow[tid] = -INFINITY; lrow[tid] = 0.f; }
    __syncthreads();

    for (int kt = 0; kt < SEQ / BKT; kt++) {
        // Load K, V tiles
        {
            int r  = tid >> 2;
            int c0 = (tid & 3) * 32;
            const float* ksrc = qkv + base + (size_t)(kt*BKT + r) * QKV_COLS + 2048 + c0;
            const float* vsrc = ksrc + HD;
            #pragma unroll
            for (int j = 0; j < 8; j++) {
                *(float4*)&Ks[r*TS + c0 + j*4] = *(const float4*)(ksrc + j*4);
                *(float4*)&Vs[r*TS + c0 + j*4] = *(const float4*)(vsrc + j*4);
            }
        }
        __syncthreads();

        // S = Q @ K^T * scale. Thread -> rows (tid>>4)+16i, cols (tid&15)+16j.
        {
            int r0 = tid >> 4;
            int c0 = tid & 15;
            float acc[4][4] = {};
            #pragma unroll 4
            for (int k = 0; k < HD; k += 4) {
                float4 qv[4], kv[4];
                #pragma unroll
                for (int i = 0; i < 4; i++) qv[i] = *(const float4*)&Qs[(r0 + 16*i)*TS + k];
                #pragma unroll
                for (int j = 0; j < 4; j++) kv[j] = *(const float4*)&Ks[(c0 + 16*j)*TS + k];
                #pragma unroll
                for (int i = 0; i < 4; i++)
                    #pragma unroll
                    for (int j = 0; j < 4; j++)
                        acc[i][j] += qv[i].x*kv[j].x + qv[i].y*kv[j].y
                                   + qv[i].z*kv[j].z + qv[i].w*kv[j].w;
            }
            #pragma unroll
            for (int i = 0; i < 4; i++)
                #pragma unroll
                for (int j = 0; j < 4; j++)
                    Ss[(r0 + 16*i)*SS + c0 + 16*j] = acc[i][j] * scale;
        }
        __syncthreads();

        // Online softmax: row = tid/4, 4 lanes per row (16 cols each), shuffle-reduce.
        {
            int r  = tid >> 2;
            int c0 = (tid & 3) * 16;
            float mloc = -INFINITY;
            #pragma unroll
            for (int j = 0; j < 16; j++) mloc = fmaxf(mloc, Ss[r*SS + c0 + j]);
            mloc = fmaxf(mloc, __shfl_xor_sync(0xffffffffu, mloc, 1));
            mloc = fmaxf(mloc, __shfl_xor_sync(0xffffffffu, mloc, 2));
            float mold = mrow[r];
            float mnew = fmaxf(mold, mloc);
            float corr = (mold == -INFINITY) ? 0.f : __expf(mold - mnew);
            float ssum = 0.f;
            #pragma unroll
            for (int j = 0; j < 16; j++) {
                float p = __expf(Ss[r*SS + c0 + j] - mnew);
                Ss[r*SS + c0 + j] = p;
                ssum += p;
            }
            ssum += __shfl_xor_sync(0xffffffffu, ssum, 1);
            ssum += __shfl_xor_sync(0xffffffffu, ssum, 2);
            if ((tid & 3) == 0) {
                mrow[r] = mnew;
                lrow[r] = lrow[r] * corr + ssum;
                crow[r] = corr;
            }
        }
        __syncthreads();

        // O = O*corr + P @ V. Thread -> 4 rows x 8 cols.
        {
            int rg = (tid >> 4) * 4;
            int c0 = (tid & 15) * 8;
            float oacc[4][8];
            #pragma unroll
            for (int i = 0; i < 4; i++) {
                float corr = crow[rg + i];
                #pragma unroll
                for (int j = 0; j < 8; j++)
                    oacc[i][j] = Os[(rg + i)*TS + c0 + j] * corr;
            }
            for (int k = 0; k < BKT; k++) {
                float p0 = Ss[(rg+0)*SS + k];
                float p1 = Ss[(rg+1)*SS + k];
                float p2 = Ss[(rg+2)*SS + k];
                float p3 = Ss[(rg+3)*SS + k];
                float4 v0 = *(const float4*)&Vs[k*TS + c0];
                float4 v1 = *(const float4*)&Vs[k*TS + c0 + 4];
                float vv[8] = {v0.x, v0.y, v0.z, v0.w, v1.x, v1.y, v1.z, v1.w};
                #pragma unroll
                for (int j = 0; j < 8; j++) {
                    oacc[0][j] += p0 * vv[j];
                    oacc[1][j] += p1 * vv[j];
                    oacc[2][j] += p2 * vv[j];
                    oacc[3][j] += p3 * vv[j];
                }
            }
            #pragma unroll
            for (int i = 0; i < 4; i++)
                #pragma unroll
                for (int j = 0; j < 8; j++)
                    Os[(rg + i)*TS + c0 + j] = oacc[i][j];
        }
        __syncthreads();
    }

    // Write out / l  -> [b, t, h*128 + d] layout
    {
        int r  = tid >> 2;
        int c0 = (tid & 3) * 32;
        float inv = 1.0f / lrow[r];
        float* dst = out + (size_t)(b*SEQ + qt*BQ + r) * NEMB + h*HD + c0;
        #pragma unroll
        for (int j = 0; j < 32; j++)
            dst[j] = Os[r*TS + c0 + j] * inv;
    }
}

// ---------------------------------------------------------------------------
extern "C" void kernel_launch(void* const* d_in, const int* in_sizes, int n_in,
                              void* d_out, int out_size) {
    const float* x      = (const float*)d_in[0];
    const float* w_attn = (const float*)d_in[1];
    const float* w_out  = (const float*)d_in[2];
    float* out = (float*)d_out;

    float *qkv, *att;
    cudaGetSymbolAddress((void**)&qkv, g_qkv);
    cudaGetSymbolAddress((void**)&att, g_att);
    cudaFuncSetAttribute(attn_kernel, cudaFuncAttributeMaxDynamicSharedMemorySize,
                         ATTN_SMEM_BYTES);

    // 1) qkv = x @ w_attn   [4096 x 2048] @ [2048 x 2304]
    dim3 g1(QKV_COLS / 128, ROWS / 128);
    sgemm_kernel<<<g1, 256>>>(x, w_attn, qkv, ROWS, QKV_COLS, NEMB);

    // 2) RoPE on q + k in place
    int rope_total = ROWS * 17 * 64;
    rope_kernel<<<(rope_total + 255) / 256, 256>>>(qkv);

    // 3) Flash attention -> g_att [4096 x 2048]
    attn_kernel<<<dim3(SEQ / BQ, NHEAD, BATCH), 256, ATTN_SMEM_BYTES>>>(qkv, att);

    // 4) out = g_att @ w_out   [4096 x 2048] @ [2048 x 2048]
    dim3 g2(NEMB / 128, ROWS / 128);
    sgemm_kernel<<<g2, 256>>>(att, w_out, out, ROWS, NEMB, NEMB);
}

// round 4
// speedup vs baseline: 1.2431x; 1.2431x over previous
#include <cuda_runtime.h>
#include <cuda_bf16.h>
#include <cstdint>
#include <math.h>

#define BATCH   2
#define SEQ     2048
#define NEMB    2048
#define NHEAD   16
#define HD      128
#define QKV_COLS 2304          // (16+2)*128
#define ROWS    (BATCH*SEQ)    // 4096

// ---------------- scratch (no cudaMalloc allowed) ----------------
__device__ float g_qkv[ROWS * QKV_COLS];
__device__ __nv_bfloat16 g_x_hi[ROWS * NEMB];
__device__ __nv_bfloat16 g_x_lo[ROWS * NEMB];
__device__ __nv_bfloat16 g_wat_hi[QKV_COLS * NEMB];   // transposed [N][K]
__device__ __nv_bfloat16 g_wat_lo[QKV_COLS * NEMB];
__device__ __nv_bfloat16 g_wot_hi[NEMB * NEMB];       // transposed [N][K]
__device__ __nv_bfloat16 g_wot_lo[NEMB * NEMB];
__device__ __nv_bfloat16 g_att_hi[ROWS * NEMB];
__device__ __nv_bfloat16 g_att_lo[ROWS * NEMB];

// ---------------- PTX helpers (baseline ISA only: sm_80-class) ----------------
__device__ __forceinline__ uint32_t smem_u32(const void* p) {
    uint32_t a;
    asm("{ .reg .u64 t; cvta.to.shared.u64 t, %1; cvt.u32.u64 %0, t; }" : "=r"(a) : "l"(p));
    return a;
}
#define CP_ASYNC16(s, g) \
    asm volatile("cp.async.cg.shared.global [%0], [%1], 16;" :: "r"(s), "l"(g) : "memory")
#define CP_COMMIT() asm volatile("cp.async.commit_group;" ::: "memory")
#define CP_WAIT1()  asm volatile("cp.async.wait_group 1;" ::: "memory")
#define CP_WAIT0()  asm volatile("cp.async.wait_group 0;" ::: "memory")
#define LDSM_X4(r, a) \
    asm volatile("ldmatrix.sync.aligned.m8n8.x4.shared.b16 {%0,%1,%2,%3}, [%4];" \
        : "=r"((r)[0]), "=r"((r)[1]), "=r"((r)[2]), "=r"((r)[3]) : "r"(a))

__device__ __forceinline__ void mma_bf16(float* d, const uint32_t* a, uint32_t b0, uint32_t b1) {
    asm volatile(
        "mma.sync.aligned.m16n8k16.row.col.f32.bf16.bf16.f32 "
        "{%0,%1,%2,%3}, {%4,%5,%6,%7}, {%8,%9}, {%0,%1,%2,%3};"
        : "+f"(d[0]), "+f"(d[1]), "+f"(d[2]), "+f"(d[3])
        : "r"(a[0]), "r"(a[1]), "r"(a[2]), "r"(a[3]), "r"(b0), "r"(b1));
}

// ---------------------------------------------------------------------------
// HMMA split-bf16 GEMM: C[M,N] fp32 = (Ah+Al)[M,K] @ (Bh+Bl)[N,K]^T
// 128x128 CTA tile, k-chunk 32, cp.async double buffer, 8 warps of 64x32.
// SMEM tile layout per buffer: [128 rows][40 bf16] (80B row stride, 16B chunks).
// ---------------------------------------------------------------------------
#define TROW_B   80                        // padded row bytes (32 bf16 + 8 pad)
#define TBUF_B   (128 * TROW_B)            // 10240 per logical tile
#define GSTAGE_B (4 * TBUF_B)              // Ah, Al, Bh, Bl
#define GEMM_SMEM (2 * GSTAGE_B)           // 81920

__global__ __launch_bounds__(256, 1) void hmma_gemm_kernel(
    const __nv_bfloat16* __restrict__ Ah, const __nv_bfloat16* __restrict__ Al,
    const __nv_bfloat16* __restrict__ Bh, const __nv_bfloat16* __restrict__ Bl,
    float* __restrict__ C, int M, int N, int K)
{
    extern __shared__ char smem[];
    const uint32_t sb = smem_u32(smem);
    const int tid  = threadIdx.x;
    const int lane = tid & 31;
    const int warp = tid >> 5;
    const int m0 = blockIdx.y * 128, n0 = blockIdx.x * 128;
    const int wm = (warp >> 2) * 64, wn = (warp & 3) * 32;

    // ---- copy thread mapping: row = tid>>1, two 16B chunks per buffer ----
    const int crow  = tid >> 1;
    const int cchk  = (tid & 1) * 2;         // chunk index 0 or 2
    const char* gsrc[4];
    gsrc[0] = (const char*)(Ah + (size_t)(m0 + crow) * K);
    gsrc[1] = (const char*)(Al + (size_t)(m0 + crow) * K);
    gsrc[2] = (const char*)(Bh + (size_t)(n0 + crow) * K);
    gsrc[3] = (const char*)(Bl + (size_t)(n0 + crow) * K);
    const uint32_t sdst = sb + crow * TROW_B + cchk * 16;

    const int nch = K / 32;

    float acc[4][4][4] = {};

    // ldmatrix addressing
    const int lr = lane & 15;                // row within 16-row group
    const int lc = lane >> 4;                // 16B half selector

    auto issue = [&](int ch) {
        const uint32_t st = (ch & 1) * GSTAGE_B;
        #pragma unroll
        for (int b = 0; b < 4; b++) {
            const char* g = gsrc[b] + (size_t)ch * 64 + cchk * 16;
            uint32_t s = sdst + st + b * TBUF_B;
            CP_ASYNC16(s, g);
            CP_ASYNC16(s + 16, g + 16);
        }
        CP_COMMIT();
    };

    issue(0);
    for (int ch = 0; ch < nch; ch++) {
        if (ch + 1 < nch) { issue(ch + 1); CP_WAIT1(); }
        else              { CP_WAIT0(); }
        __syncthreads();

        const uint32_t stage = sb + (ch & 1) * GSTAGE_B;
        const uint32_t aoff  = stage + (wm + lr) * TROW_B + lc * 16;
        const uint32_t boff  = stage + 2 * TBUF_B + (wn + lr) * TROW_B + lc * 16;

        #pragma unroll
        for (int kh = 0; kh < 2; kh++) {
            const uint32_t ko = kh * 32;
            uint32_t ah[4][4], al[4][4], bh[2][4], bl[2][4];
            #pragma unroll
            for (int ma = 0; ma < 4; ma++) {
                uint32_t ad = aoff + ma * (16 * TROW_B) + ko;
                LDSM_X4(ah[ma], ad);
                LDSM_X4(al[ma], ad + TBUF_B);
            }
            #pragma unroll
            for (int ng = 0; ng < 2; ng++) {
                uint32_t bd = boff + ng * (16 * TROW_B) + ko;
                LDSM_X4(bh[ng], bd);
                LDSM_X4(bl[ng], bd + TBUF_B);
            }
            #pragma unroll
            for (int ma = 0; ma < 4; ma++)
                #pragma unroll
                for (int na = 0; na < 4; na++) {
                    const int ng = na >> 1, hi = na & 1;
                    mma_bf16(acc[ma][na], ah[ma], bh[ng][hi], bh[ng][hi + 2]);
                    mma_bf16(acc[ma][na], ah[ma], bl[ng][hi], bl[ng][hi + 2]);
                    mma_bf16(acc[ma][na], al[ma], bh[ng][hi], bh[ng][hi + 2]);
                }
        }
        __syncthreads();
    }

    // ---- epilogue: fp32 C ----
    const int gr = lane >> 2, gc = (lane & 3) * 2;
    #pragma unroll
    for (int ma = 0; ma < 4; ma++) {
        #pragma unroll
        for (int na = 0; na < 4; na++) {
            size_t r = (size_t)(m0 + wm + ma * 16 + gr);
            size_t c = (size_t)(n0 + wn + na * 8 + gc);
            *(float2*)&C[r * N + c]       = make_float2(acc[ma][na][0], acc[ma][na][1]);
            *(float2*)&C[(r + 8) * N + c] = make_float2(acc[ma][na][2], acc[ma][na][3]);
        }
    }
}

// ---------------------------------------------------------------------------
// fp32 -> bf16 hi/lo split (same layout)
// ---------------------------------------------------------------------------
__global__ void split_kernel(const float* __restrict__ in,
                             __nv_bfloat16* __restrict__ hi,
                             __nv_bfloat16* __restrict__ lo, int n) {
    int i = (blockIdx.x * blockDim.x + threadIdx.x) * 4;
    if (i >= n) return;
    float4 v = *(const float4*)(in + i);
    __nv_bfloat16 h0 = __float2bfloat16(v.x), h1 = __float2bfloat16(v.y);
    __nv_bfloat16 h2 = __float2bfloat16(v.z), h3 = __float2bfloat16(v.w);
    __nv_bfloat162* H = (__nv_bfloat162*)(hi + i);
    __nv_bfloat162* L = (__nv_bfloat162*)(lo + i);
    H[0] = __nv_bfloat162(h0, h1); H[1] = __nv_bfloat162(h2, h3);
    L[0] = __nv_bfloat162(__float2bfloat16(v.x - __bfloat162float(h0)),
                          __float2bfloat16(v.y - __bfloat162float(h1)));
    L[1] = __nv_bfloat162(__float2bfloat16(v.z - __bfloat162float(h2)),
                          __float2bfloat16(v.w - __bfloat162float(h3)));
}

// ---------------------------------------------------------------------------
// transpose + split: w[K][N] fp32 -> hi/lo[N][K] bf16
// ---------------------------------------------------------------------------
__global__ void transpose_split_kernel(const float* __restrict__ w,
                                       __nv_bfloat16* __restrict__ hi,
                                       __nv_bfloat16* __restrict__ lo,
                                       int K, int N) {
    __shared__ float t[32][33];
    int n0 = blockIdx.x * 32, k0 = blockIdx.y * 32;
    int tx = threadIdx.x, ty = threadIdx.y;
    #pragma unroll
    for (int r = ty; r < 32; r += 8)
        t[r][tx] = w[(size_t)(k0 + r) * N + n0 + tx];
    __syncthreads();
    #pragma unroll
    for (int r = ty; r < 32; r += 8) {
        float v = t[tx][r];
        __nv_bfloat16 h = __float2bfloat16(v);
        size_t o = (size_t)(n0 + r) * K + k0 + tx;
        hi[o] = h;
        lo[o] = __float2bfloat16(v - __bfloat162float(h));
    }
}

// ---------------------------------------------------------------------------
// RoPE in place on q (heads 0..15) and k (offset 2048) inside g_qkv.
// ---------------------------------------------------------------------------
__global__ void rope_kernel(float* __restrict__ qkv) {
    const int total = ROWS * 17 * 64;
    int idx = blockIdx.x * blockDim.x + threadIdx.x;
    if (idx >= total) return;
    int i    = idx & 63;
    int head = (idx >> 6) % 17;
    int row  = idx / (17 * 64);
    int t    = row & (SEQ - 1);
    int off  = (head < 16) ? head * HD : 2048;
    float* p = qkv + (size_t)row * QKV_COLS + off;
    float freq = expf(-(4.0f * (float)i + 1.0f) * (9.210340371976184f / 128.0f));
    float ang = (float)t * freq;
    float c = cosf(ang), s = sinf(ang);
    float x1 = p[i], x2 = p[i + 64];
    p[i]      = x1 * c - x2 * s;
    p[i + 64] = x2 * c + x1 * s;
}

// ---------------------------------------------------------------------------
// Flash attention (non-causal), fp32 SIMT; epilogue writes bf16 hi/lo.
// ---------------------------------------------------------------------------
#define BQ 64
#define BKT 64
#define TS 132
#define SS 68
#define ATTN_SMEM_FLOATS (4*BQ*TS + BQ*SS + 3*BQ)
#define ATTN_SMEM_BYTES  (ATTN_SMEM_FLOATS * 4)

__global__ __launch_bounds__(256) void attn_kernel(const float* __restrict__ qkv,
                                                   __nv_bfloat16* __restrict__ out_hi,
                                                   __nv_bfloat16* __restrict__ out_lo) {
    const int qt  = blockIdx.x;
    const int h   = blockIdx.y;
    const int b   = blockIdx.z;
    const int tid = threadIdx.x;

    extern __shared__ float sm[];
    float* Qs   = sm;
    float* Ks   = Qs + BQ*TS;
    float* Vs   = Ks + BKT*TS;
    float* Os   = Vs + BKT*TS;
    float* Ss   = Os + BQ*TS;
    float* mrow = Ss + BQ*SS;
    float* lrow = mrow + BQ;
    float* crow = lrow + BQ;

    const float scale = 0.08838834764831845f;
    const size_t base = (size_t)b * SEQ * QKV_COLS;

    {
        int r  = tid >> 2;
        int c0 = (tid & 3) * 32;
        const float* src = qkv + base + (size_t)(qt*BQ + r) * QKV_COLS + h*HD + c0;
        #pragma unroll
        for (int j = 0; j < 8; j++) {
            *(float4*)&Qs[r*TS + c0 + j*4] = *(const float4*)(src + j*4);
            *(float4*)&Os[r*TS + c0 + j*4] = make_float4(0.f, 0.f, 0.f, 0.f);
        }
    }
    if (tid < BQ) { mrow[tid] = -INFINITY; lrow[tid] = 0.f; }
    __syncthreads();

    for (int kt = 0; kt < SEQ / BKT; kt++) {
        {
            int r  = tid >> 2;
            int c0 = (tid & 3) * 32;
            const float* ksrc = qkv + base + (size_t)(kt*BKT + r) * QKV_COLS + 2048 + c0;
            const float* vsrc = ksrc + HD;
            #pragma unroll
            for (int j = 0; j < 8; j++) {
                *(float4*)&Ks[r*TS + c0 + j*4] = *(const float4*)(ksrc + j*4);
                *(float4*)&Vs[r*TS + c0 + j*4] = *(const float4*)(vsrc + j*4);
            }
        }
        __syncthreads();

        {
            int r0 = tid >> 4;
            int c0 = tid & 15;
            float acc[4][4] = {};
            #pragma unroll 4
            for (int k = 0; k < HD; k += 4) {
                float4 qv[4], kv[4];
                #pragma unroll
                for (int i = 0; i < 4; i++) qv[i] = *(const float4*)&Qs[(r0 + 16*i)*TS + k];
                #pragma unroll
                for (int j = 0; j < 4; j++) kv[j] = *(const float4*)&Ks[(c0 + 16*j)*TS + k];
                #pragma unroll
                for (int i = 0; i < 4; i++)
                    #pragma unroll
                    for (int j = 0; j < 4; j++)
                        acc[i][j] += qv[i].x*kv[j].x + qv[i].y*kv[j].y
                                   + qv[i].z*kv[j].z + qv[i].w*kv[j].w;
            }
            #pragma unroll
            for (int i = 0; i < 4; i++)
                #pragma unroll
                for (int j = 0; j < 4; j++)
                    Ss[(r0 + 16*i)*SS + c0 + 16*j] = acc[i][j] * scale;
        }
        __syncthreads();

        {
            int r  = tid >> 2;
            int c0 = (tid & 3) * 16;
            float mloc = -INFINITY;
            #pragma unroll
            for (int j = 0; j < 16; j++) mloc = fmaxf(mloc, Ss[r*SS + c0 + j]);
            mloc = fmaxf(mloc, __shfl_xor_sync(0xffffffffu, mloc, 1));
            mloc = fmaxf(mloc, __shfl_xor_sync(0xffffffffu, mloc, 2));
            float mold = mrow[r];
            float mnew = fmaxf(mold, mloc);
            float corr = (mold == -INFINITY) ? 0.f : __expf(mold - mnew);
            float ssum = 0.f;
            #pragma unroll
            for (int j = 0; j < 16; j++) {
                float p = __expf(Ss[r*SS + c0 + j] - mnew);
                Ss[r*SS + c0 + j] = p;
                ssum += p;
            }
            ssum += __shfl_xor_sync(0xffffffffu, ssum, 1);
            ssum += __shfl_xor_sync(0xffffffffu, ssum, 2);
            if ((tid & 3) == 0) {
                mrow[r] = mnew;
                lrow[r] = lrow[r] * corr + ssum;
                crow[r] = corr;
            }
        }
        __syncthreads();

        {
            int rg = (tid >> 4) * 4;
            int c0 = (tid & 15) * 8;
            float oacc[4][8];
            #pragma unroll
            for (int i = 0; i < 4; i++) {
                float corr = crow[rg + i];
                #pragma unroll
                for (int j = 0; j < 8; j++)
                    oacc[i][j] = Os[(rg + i)*TS + c0 + j] * corr;
            }
            for (int k = 0; k < BKT; k++) {
                float p0 = Ss[(rg+0)*SS + k];
                float p1 = Ss[(rg+1)*SS + k];
                float p2 = Ss[(rg+2)*SS + k];
                float p3 = Ss[(rg+3)*SS + k];
                float4 v0 = *(const float4*)&Vs[k*TS + c0];
                float4 v1 = *(const float4*)&Vs[k*TS + c0 + 4];
                float vv[8] = {v0.x, v0.y, v0.z, v0.w, v1.x, v1.y, v1.z, v1.w};
                #pragma unroll
                for (int j = 0; j < 8; j++) {
                    oacc[0][j] += p0 * vv[j];
                    oacc[1][j] += p1 * vv[j];
                    oacc[2][j] += p2 * vv[j];
                    oacc[3][j] += p3 * vv[j];
                }
            }
            #pragma unroll
            for (int i = 0; i < 4; i++)
                #pragma unroll
                for (int j = 0; j < 8; j++)
                    Os[(rg + i)*TS + c0 + j] = oacc[i][j];
        }
        __syncthreads();
    }

    {
        int r  = tid >> 2;
        int c0 = (tid & 3) * 32;
        float inv = 1.0f / lrow[r];
        size_t o = (size_t)(b*SEQ + qt*BQ + r) * NEMB + h*HD + c0;
        #pragma unroll
        for (int j = 0; j < 32; j++) {
            float v = Os[r*TS + c0 + j] * inv;
            __nv_bfloat16 hh = __float2bfloat16(v);
            out_hi[o + j] = hh;
            out_lo[o + j] = __float2bfloat16(v - __bfloat162float(hh));
        }
    }
}

// ---------------------------------------------------------------------------
extern "C" void kernel_launch(void* const* d_in, const int* in_sizes, int n_in,
                              void* d_out, int out_size) {
    const float* x      = (const float*)d_in[0];
    const float* w_attn = (const float*)d_in[1];
    const float* w_out  = (const float*)d_in[2];
    float* out = (float*)d_out;

    float *qkv;
    __nv_bfloat16 *xhi, *xlo, *wath, *watl, *woth, *wotl, *atth, *attl;
    cudaGetSymbolAddress((void**)&qkv,  g_qkv);
    cudaGetSymbolAddress((void**)&xhi,  g_x_hi);
    cudaGetSymbolAddress((void**)&xlo,  g_x_lo);
    cudaGetSymbolAddress((void**)&wath, g_wat_hi);
    cudaGetSymbolAddress((void**)&watl, g_wat_lo);
    cudaGetSymbolAddress((void**)&woth, g_wot_hi);
    cudaGetSymbolAddress((void**)&wotl, g_wot_lo);
    cudaGetSymbolAddress((void**)&atth, g_att_hi);
    cudaGetSymbolAddress((void**)&attl, g_att_lo);

    cudaFuncSetAttribute(attn_kernel, cudaFuncAttributeMaxDynamicSharedMemorySize, ATTN_SMEM_BYTES);
    cudaFuncSetAttribute(hmma_gemm_kernel, cudaFuncAttributeMaxDynamicSharedMemorySize, GEMM_SMEM);

    // 0) precision splits
    int nx = ROWS * NEMB;
    split_kernel<<<nx / (4 * 256), 256>>>(x, xhi, xlo, nx);
    transpose_split_kernel<<<dim3(QKV_COLS / 32, NEMB / 32), dim3(32, 8)>>>(w_attn, wath, watl, NEMB, QKV_COLS);
    transpose_split_kernel<<<dim3(NEMB / 32, NEMB / 32), dim3(32, 8)>>>(w_out, woth, wotl, NEMB, NEMB);

    // 1) qkv = x @ w_attn  (HMMA split-bf16)
    hmma_gemm_kernel<<<dim3(QKV_COLS / 128, ROWS / 128), 256, GEMM_SMEM>>>(
        xhi, xlo, wath, watl, qkv, ROWS, QKV_COLS, NEMB);

    // 2) RoPE in place
    int rope_total = ROWS * 17 * 64;
    rope_kernel<<<(rope_total + 255) / 256, 256>>>(qkv);

    // 3) flash attention -> bf16 hi/lo
    attn_kernel<<<dim3(SEQ / BQ, NHEAD, BATCH), 256, ATTN_SMEM_BYTES>>>(qkv, atth, attl);

    // 4) out = att @ w_out  (HMMA split-bf16)
    hmma_gemm_kernel<<<dim3(NEMB / 128, ROWS / 128), 256, GEMM_SMEM>>>(
        atth, attl, woth, wotl, out, ROWS, NEMB, NEMB);
}

// round 9
// speedup vs baseline: 3.0671x; 2.4673x over previous
#include <cuda_runtime.h>
#include <cuda_bf16.h>
#include <cstdint>
#include <math.h>

#define BATCH   2
#define SEQ     2048
#define NEMB    2048
#define NHEAD   16
#define HD      128
#define QKV_COLS 2304          // (16+2)*128
#define ROWS    (BATCH*SEQ)    // 4096

// ---------------- scratch (no cudaMalloc allowed) ----------------
__device__ float g_qkv[ROWS * QKV_COLS];
__device__ __nv_bfloat16 g_x_hi[ROWS * NEMB];
__device__ __nv_bfloat16 g_x_lo[ROWS * NEMB];
__device__ __nv_bfloat16 g_wat_hi[QKV_COLS * NEMB];   // transposed [N][K]
__device__ __nv_bfloat16 g_wat_lo[QKV_COLS * NEMB];
__device__ __nv_bfloat16 g_wot_hi[NEMB * NEMB];       // transposed [N][K]
__device__ __nv_bfloat16 g_wot_lo[NEMB * NEMB];
__device__ __nv_bfloat16 g_att_hi[ROWS * NEMB];
__device__ __nv_bfloat16 g_att_lo[ROWS * NEMB];
__device__ __nv_bfloat16 g_q_hi[ROWS * NEMB];         // post-RoPE q
__device__ __nv_bfloat16 g_q_lo[ROWS * NEMB];
__device__ __nv_bfloat16 g_k_hi[ROWS * HD];           // post-RoPE k [b*SEQ+t][128]
__device__ __nv_bfloat16 g_k_lo[ROWS * HD];
__device__ __nv_bfloat16 g_vt_hi[BATCH * HD * SEQ];   // v transposed [b][d][t]
__device__ __nv_bfloat16 g_vt_lo[BATCH * HD * SEQ];

// ---------------- PTX helpers (baseline ISA only: sm_80-class) ----------------
__device__ __forceinline__ uint32_t smem_u32(const void* p) {
    uint32_t a;
    asm("{ .reg .u64 t; cvta.to.shared.u64 t, %1; cvt.u32.u64 %0, t; }" : "=r"(a) : "l"(p));
    return a;
}
#define CP_ASYNC16(s, g) \
    asm volatile("cp.async.cg.shared.global [%0], [%1], 16;" :: "r"(s), "l"(g) : "memory")
#define CP_COMMIT() asm volatile("cp.async.commit_group;" ::: "memory")
#define CP_WAIT1()  asm volatile("cp.async.wait_group 1;" ::: "memory")
#define CP_WAIT0()  asm volatile("cp.async.wait_group 0;" ::: "memory")
#define LDSM_X4(r, a) \
    asm volatile("ldmatrix.sync.aligned.m8n8.x4.shared.b16 {%0,%1,%2,%3}, [%4];" \
        : "=r"((r)[0]), "=r"((r)[1]), "=r"((r)[2]), "=r"((r)[3]) : "r"(a))

__device__ __forceinline__ void mma_bf16(float* d, const uint32_t* a, uint32_t b0, uint32_t b1) {
    asm volatile(
        "mma.sync.aligned.m16n8k16.row.col.f32.bf16.bf16.f32 "
        "{%0,%1,%2,%3}, {%4,%5,%6,%7}, {%8,%9}, {%0,%1,%2,%3};"
        : "+f"(d[0]), "+f"(d[1]), "+f"(d[2]), "+f"(d[3])
        : "r"(a[0]), "r"(a[1]), "r"(a[2]), "r"(a[3]), "r"(b0), "r"(b1));
}
__device__ __forceinline__ uint32_t pack_bf16(float x, float y) {
    __nv_bfloat162 t = __floats2bfloat162_rn(x, y);
    return *(uint32_t*)&t;
}

// ---------------------------------------------------------------------------
// HMMA split-bf16 GEMM: C[M,N] fp32 = (Ah+Al)[M,K] @ (Bh+Bl)[N,K]^T
// ---------------------------------------------------------------------------
#define TROW_B   80
#define TBUF_B   (128 * TROW_B)
#define GSTAGE_B (4 * TBUF_B)
#define GEMM_SMEM (2 * GSTAGE_B)

__global__ __launch_bounds__(256, 1) void hmma_gemm_kernel(
    const __nv_bfloat16* __restrict__ Ah, const __nv_bfloat16* __restrict__ Al,
    const __nv_bfloat16* __restrict__ Bh, const __nv_bfloat16* __restrict__ Bl,
    float* __restrict__ C, int M, int N, int K)
{
    extern __shared__ char smem[];
    const uint32_t sb = smem_u32(smem);
    const int tid  = threadIdx.x;
    const int lane = tid & 31;
    const int warp = tid >> 5;
    const int m0 = blockIdx.y * 128, n0 = blockIdx.x * 128;
    const int wm = (warp >> 2) * 64, wn = (warp & 3) * 32;

    const int crow  = tid >> 1;
    const int cchk  = (tid & 1) * 2;
    const char* gsrc[4];
    gsrc[0] = (const char*)(Ah + (size_t)(m0 + crow) * K);
    gsrc[1] = (const char*)(Al + (size_t)(m0 + crow) * K);
    gsrc[2] = (const char*)(Bh + (size_t)(n0 + crow) * K);
    gsrc[3] = (const char*)(Bl + (size_t)(n0 + crow) * K);
    const uint32_t sdst = sb + crow * TROW_B + cchk * 16;

    const int nch = K / 32;
    float acc[4][4][4] = {};
    const int lr = lane & 15;
    const int lc = lane >> 4;

    auto issue = [&](int ch) {
        const uint32_t st = (ch & 1) * GSTAGE_B;
        #pragma unroll
        for (int b = 0; b < 4; b++) {
            const char* g = gsrc[b] + (size_t)ch * 64 + cchk * 16;
            uint32_t s = sdst + st + b * TBUF_B;
            CP_ASYNC16(s, g);
            CP_ASYNC16(s + 16, g + 16);
        }
        CP_COMMIT();
    };

    issue(0);
    for (int ch = 0; ch < nch; ch++) {
        if (ch + 1 < nch) { issue(ch + 1); CP_WAIT1(); }
        else              { CP_WAIT0(); }
        __syncthreads();

        const uint32_t stage = sb + (ch & 1) * GSTAGE_B;
        const uint32_t aoff  = stage + (wm + lr) * TROW_B + lc * 16;
        const uint32_t boff  = stage + 2 * TBUF_B + (wn + lr) * TROW_B + lc * 16;

        #pragma unroll
        for (int kh = 0; kh < 2; kh++) {
            const uint32_t ko = kh * 32;
            uint32_t ah[4][4], al[4][4], bh[2][4], bl[2][4];
            #pragma unroll
            for (int ma = 0; ma < 4; ma++) {
                uint32_t ad = aoff + ma * (16 * TROW_B) + ko;
                LDSM_X4(ah[ma], ad);
                LDSM_X4(al[ma], ad + TBUF_B);
            }
            #pragma unroll
            for (int ng = 0; ng < 2; ng++) {
                uint32_t bd = boff + ng * (16 * TROW_B) + ko;
                LDSM_X4(bh[ng], bd);
                LDSM_X4(bl[ng], bd + TBUF_B);
            }
            #pragma unroll
            for (int ma = 0; ma < 4; ma++)
                #pragma unroll
                for (int na = 0; na < 4; na++) {
                    const int ng = na >> 1, hi = na & 1;
                    mma_bf16(acc[ma][na], ah[ma], bh[ng][hi], bh[ng][hi + 2]);
                    mma_bf16(acc[ma][na], ah[ma], bl[ng][hi], bl[ng][hi + 2]);
                    mma_bf16(acc[ma][na], al[ma], bh[ng][hi], bh[ng][hi + 2]);
                }
        }
        __syncthreads();
    }

    const int gr = lane >> 2, gc = (lane & 3) * 2;
    #pragma unroll
    for (int ma = 0; ma < 4; ma++) {
        #pragma unroll
        for (int na = 0; na < 4; na++) {
            size_t r = (size_t)(m0 + wm + ma * 16 + gr);
            size_t c = (size_t)(n0 + wn + na * 8 + gc);
            *(float2*)&C[r * N + c]       = make_float2(acc[ma][na][0], acc[ma][na][1]);
            *(float2*)&C[(r + 8) * N + c] = make_float2(acc[ma][na][2], acc[ma][na][3]);
        }
    }
}

// ---------------------------------------------------------------------------
// HMMA flash attention (no-max softmax), split-bf16 everywhere.
// Block = (128 q rows, head, batch), 8 warps x (16 rows x 32 keys).
// ---------------------------------------------------------------------------
#define QSTR 272
#define KSTR 272
#define VSTR 80
#define SM_QB  (128*QSTR)           // per-split Q bytes (34816)
#define SM_K   (2*SM_QB)            // 69632
#define KBUF   (32*KSTR)            // 8704
#define KSTAGE (2*KBUF)             // 17408
#define SM_V   (SM_K + 2*KSTAGE)    // 104448
#define VBUF   (128*VSTR)           // 10240
#define VSTAGE (2*VBUF)             // 20480
#define ATT_SMEM (SM_V + 2*VSTAGE)  // 145408

__global__ __launch_bounds__(256, 1) void hmma_attn_kernel(
    const __nv_bfloat16* __restrict__ qh_g, const __nv_bfloat16* __restrict__ ql_g,
    const __nv_bfloat16* __restrict__ kh_g, const __nv_bfloat16* __restrict__ kl_g,
    const __nv_bfloat16* __restrict__ vth_g, const __nv_bfloat16* __restrict__ vtl_g,
    __nv_bfloat16* __restrict__ oh_g, __nv_bfloat16* __restrict__ ol_g)
{
    extern __shared__ char smem[];
    const uint32_t sb = smem_u32(smem);
    const int qt = blockIdx.x, h = blockIdx.y, b = blockIdx.z;
    const int tid = threadIdx.x, lane = tid & 31, warp = tid >> 5;
    const int lr = lane & 15, lc = lane >> 4;
    const int gr = lane >> 2, gc = (lane & 3) * 2;

    // Q tile cp.async (both splits), part of group 0
    {
        const char* s0 = (const char*)(qh_g + (size_t)(b * SEQ + qt * 128) * NEMB + h * 128);
        const char* s1 = (const char*)(ql_g + (size_t)(b * SEQ + qt * 128) * NEMB + h * 128);
        #pragma unroll
        for (int i = 0; i < 8; i++) {
            int c = tid + i * 256;
            int row = c >> 4, off = (c & 15) * 16;
            CP_ASYNC16(sb + row * QSTR + off,         s0 + (size_t)row * (NEMB * 2) + off);
            CP_ASYNC16(sb + SM_QB + row * QSTR + off, s1 + (size_t)row * (NEMB * 2) + off);
        }
    }
    auto issue = [&](int kt) {
        uint32_t kb = sb + SM_K + (kt & 1) * KSTAGE;
        uint32_t vb = sb + SM_V + (kt & 1) * VSTAGE;
        const char* ksh = (const char*)(kh_g + (size_t)(b * SEQ + kt * 32) * HD);
        const char* ksl = (const char*)(kl_g + (size_t)(b * SEQ + kt * 32) * HD);
        #pragma unroll
        for (int i = 0; i < 2; i++) {
            int c = tid + i * 256;
            int row = c >> 4, off = (c & 15) * 16;
            CP_ASYNC16(kb + row * KSTR + off,        ksh + (size_t)row * 256 + off);
            CP_ASYNC16(kb + KBUF + row * KSTR + off, ksl + (size_t)row * 256 + off);
        }
        const char* vsh = (const char*)(vth_g + (size_t)b * HD * SEQ + kt * 32);
        const char* vsl = (const char*)(vtl_g + (size_t)b * HD * SEQ + kt * 32);
        #pragma unroll
        for (int i = 0; i < 2; i++) {
            int c = tid + i * 256;
            int row = c >> 2, off = (c & 3) * 16;
            CP_ASYNC16(vb + row * VSTR + off,        vsh + (size_t)row * (SEQ * 2) + off);
            CP_ASYNC16(vb + VBUF + row * VSTR + off, vsl + (size_t)row * (SEQ * 2) + off);
        }
    };
    issue(0); CP_COMMIT();
    issue(1); CP_COMMIT();

    float oacc[16][4] = {};
    float lsum0 = 0.f, lsum1 = 0.f;
    const float SC2 = 0.08838834764831845f * 1.44269504088896f;  // scale * log2(e)

    const uint32_t qah = sb + (warp * 16 + lr) * QSTR + lc * 16;
    const uint32_t qal = qah + SM_QB;

    const int NKT = SEQ / 32;
    for (int kt = 0; kt < NKT; kt++) {
        if (kt == NKT - 1) { CP_WAIT0(); } else { CP_WAIT1(); }
        __syncthreads();
        const uint32_t kb = sb + SM_K + (kt & 1) * KSTAGE;
        const uint32_t vb = sb + SM_V + (kt & 1) * VSTAGE;

        // ---- S = Q @ K^T (split: hh + hl + lh) ----
        float sacc[4][4] = {};
        #pragma unroll
        for (int kh = 0; kh < 8; kh++) {
            uint32_t qfh[4], qfl[4], kfh[2][4], kfl[2][4];
            LDSM_X4(qfh, qah + kh * 32);
            LDSM_X4(qfl, qal + kh * 32);
            #pragma unroll
            for (int g = 0; g < 2; g++) {
                uint32_t ka = kb + (g * 16 + lr) * KSTR + kh * 32 + lc * 16;
                LDSM_X4(kfh[g], ka);
                LDSM_X4(kfl[g], ka + KBUF);
            }
            #pragma unroll
            for (int na = 0; na < 4; na++) {
                const int g = na >> 1, hi = na & 1;
                mma_bf16(sacc[na], qfh, kfh[g][hi], kfh[g][hi + 2]);
                mma_bf16(sacc[na], qfh, kfl[g][hi], kfl[g][hi + 2]);
                mma_bf16(sacc[na], qfl, kfh[g][hi], kfh[g][hi + 2]);
            }
        }

        // ---- P = exp(S*scale); accumulate row sums; build split A-frags ----
        uint32_t pah[2][4], pal[2][4];
        float l0 = 0.f, l1 = 0.f;
        #pragma unroll
        for (int na = 0; na < 4; na++) {
            float p0 = exp2f(sacc[na][0] * SC2);
            float p1 = exp2f(sacc[na][1] * SC2);
            float p2 = exp2f(sacc[na][2] * SC2);
            float p3 = exp2f(sacc[na][3] * SC2);
            l0 += p0 + p1; l1 += p2 + p3;
            const int t = na >> 1, half = na & 1;
            __nv_bfloat16 h0 = __float2bfloat16(p0), h1 = __float2bfloat16(p1);
            __nv_bfloat16 h2 = __float2bfloat16(p2), h3 = __float2bfloat16(p3);
            pah[t][half * 2 + 0] = pack_bf16(__bfloat162float(h0), __bfloat162float(h1));
            pah[t][half * 2 + 1] = pack_bf16(__bfloat162float(h2), __bfloat162float(h3));
            pal[t][half * 2 + 0] = pack_bf16(p0 - __bfloat162float(h0), p1 - __bfloat162float(h1));
            pal[t][half * 2 + 1] = pack_bf16(p2 - __bfloat162float(h2), p3 - __bfloat162float(h3));
        }
        l0 += __shfl_xor_sync(0xffffffffu, l0, 1);
        l0 += __shfl_xor_sync(0xffffffffu, l0, 2);
        l1 += __shfl_xor_sync(0xffffffffu, l1, 1);
        l1 += __shfl_xor_sync(0xffffffffu, l1, 2);
        lsum0 += l0; lsum1 += l1;

        // ---- O += P @ V (split: hh + hl + lh) ----
        #pragma unroll
        for (int nb8 = 0; nb8 < 8; nb8++) {
            uint32_t vfh[2][4], vfl[2][4];
            #pragma unroll
            for (int ka = 0; ka < 2; ka++) {
                uint32_t va = vb + (nb8 * 16 + lr) * VSTR + ka * 32 + lc * 16;
                LDSM_X4(vfh[ka], va);
                LDSM_X4(vfl[ka], va + VBUF);
            }
            #pragma unroll
            for (int ns = 0; ns < 2; ns++) {
                const int n = nb8 * 2 + ns;
                #pragma unroll
                for (int t = 0; t < 2; t++) {
                    mma_bf16(oacc[n], pah[t], vfh[t][ns], vfh[t][ns + 2]);
                    mma_bf16(oacc[n], pah[t], vfl[t][ns], vfl[t][ns + 2]);
                    mma_bf16(oacc[n], pal[t], vfh[t][ns], vfh[t][ns + 2]);
                }
            }
        }
        __syncthreads();
        if (kt + 2 < NKT) { issue(kt + 2); CP_COMMIT(); }
    }

    // ---- epilogue: normalize, split to bf16 hi/lo ----
    const float inv0 = 1.f / lsum0, inv1 = 1.f / lsum1;
    const size_t row0 = (size_t)(b * SEQ + qt * 128 + warp * 16 + gr);
    #pragma unroll
    for (int n = 0; n < 16; n++) {
        const size_t col = (size_t)h * 128 + n * 8 + gc;
        float v0 = oacc[n][0] * inv0, v1 = oacc[n][1] * inv0;
        float v2 = oacc[n][2] * inv1, v3 = oacc[n][3] * inv1;
        __nv_bfloat16 h0 = __float2bfloat16(v0), h1 = __float2bfloat16(v1);
        __nv_bfloat16 h2 = __float2bfloat16(v2), h3 = __float2bfloat16(v3);
        *(uint32_t*)&oh_g[row0 * NEMB + col] = pack_bf16(__bfloat162float(h0), __bfloat162float(h1));
        *(uint32_t*)&ol_g[row0 * NEMB + col] = pack_bf16(v0 - __bfloat162float(h0), v1 - __bfloat162float(h1));
        *(uint32_t*)&oh_g[(row0 + 8) * NEMB + col] = pack_bf16(__bfloat162float(h2), __bfloat162float(h3));
        *(uint32_t*)&ol_g[(row0 + 8) * NEMB + col] = pack_bf16(v2 - __bfloat162float(h2), v3 - __bfloat162float(h3));
    }
}

// ---------------------------------------------------------------------------
// fp32 -> bf16 hi/lo split
// ---------------------------------------------------------------------------
__global__ void split_kernel(const float* __restrict__ in,
                             __nv_bfloat16* __restrict__ hi,
                             __nv_bfloat16* __restrict__ lo, int n) {
    int i = (blockIdx.x * blockDim.x + threadIdx.x) * 4;
    if (i >= n) return;
    float4 v = *(const float4*)(in + i);
    __nv_bfloat16 h0 = __float2bfloat16(v.x), h1 = __float2bfloat16(v.y);
    __nv_bfloat16 h2 = __float2bfloat16(v.z), h3 = __float2bfloat16(v.w);
    __nv_bfloat162* H = (__nv_bfloat162*)(hi + i);
    __nv_bfloat162* L = (__nv_bfloat162*)(lo + i);
    H[0] = __nv_bfloat162(h0, h1); H[1] = __nv_bfloat162(h2, h3);
    L[0] = __nv_bfloat162(__float2bfloat16(v.x - __bfloat162float(h0)),
                          __float2bfloat16(v.y - __bfloat162float(h1)));
    L[1] = __nv_bfloat162(__float2bfloat16(v.z - __bfloat162float(h2)),
                          __float2bfloat16(v.w - __bfloat162float(h3)));
}

// ---------------------------------------------------------------------------
// transpose + split: w[K][N] fp32 -> hi/lo[N][K] bf16
// ---------------------------------------------------------------------------
__global__ void transpose_split_kernel(const float* __restrict__ w,
                                       __nv_bfloat16* __restrict__ hi,
                                       __nv_bfloat16* __restrict__ lo,
                                       int K, int N) {
    __shared__ float t[32][33];
    int n0 = blockIdx.x * 32, k0 = blockIdx.y * 32;
    int tx = threadIdx.x, ty = threadIdx.y;
    #pragma unroll
    for (int r = ty; r < 32; r += 8)
        t[r][tx] = w[(size_t)(k0 + r) * N + n0 + tx];
    __syncthreads();
    #pragma unroll
    for (int r = ty; r < 32; r += 8) {
        float v = t[tx][r];
        __nv_bfloat16 h = __float2bfloat16(v);
        size_t o = (size_t)(n0 + r) * K + k0 + tx;
        hi[o] = h;
        lo[o] = __float2bfloat16(v - __bfloat162float(h));
    }
}

// ---------------------------------------------------------------------------
// RoPE + split q,k -> bf16 hi/lo
// ---------------------------------------------------------------------------
__global__ void rope_split_kernel(const float* __restrict__ qkv,
                                  __nv_bfloat16* __restrict__ qh, __nv_bfloat16* __restrict__ ql,
                                  __nv_bfloat16* __restrict__ kh, __nv_bfloat16* __restrict__ kl) {
    const int total = ROWS * 17 * 64;
    int idx = blockIdx.x * blockDim.x + threadIdx.x;
    if (idx >= total) return;
    int i    = idx & 63;
    int head = (idx >> 6) % 17;
    int row  = idx / (17 * 64);
    int t    = row & (SEQ - 1);
    int off  = (head < 16) ? head * HD : 2048;
    const float* p = qkv + (size_t)row * QKV_COLS + off;
    float freq = expf(-(4.0f * (float)i + 1.0f) * (9.210340371976184f / 128.0f));
    float ang = (float)t * freq;
    float c = cosf(ang), s = sinf(ang);
    float x1 = p[i], x2 = p[i + 64];
    float y1 = x1 * c - x2 * s;
    float y2 = x2 * c + x1 * s;
    __nv_bfloat16 h1 = __float2bfloat16(y1), h2 = __float2bfloat16(y2);
    if (head < 16) {
        size_t o = (size_t)row * NEMB + head * HD;
        qh[o + i]      = h1;  ql[o + i]      = __float2bfloat16(y1 - __bfloat162float(h1));
        qh[o + i + 64] = h2;  ql[o + i + 64] = __float2bfloat16(y2 - __bfloat162float(h2));
    } else {
        size_t o = (size_t)row * HD;
        kh[o + i]      = h1;  kl[o + i]      = __float2bfloat16(y1 - __bfloat162float(h1));
        kh[o + i + 64] = h2;  kl[o + i + 64] = __float2bfloat16(y2 - __bfloat162float(h2));
    }
}

// ---------------------------------------------------------------------------
// V transpose + split: qkv[b*SEQ+t][2176+d] -> vt[b][d][t] bf16 hi/lo
// ---------------------------------------------------------------------------
__global__ void vt_split_kernel(const float* __restrict__ qkv,
                                __nv_bfloat16* __restrict__ vth,
                                __nv_bfloat16* __restrict__ vtl) {
    __shared__ float tile[32][33];
    int t0 = blockIdx.x * 32, d0 = blockIdx.y * 32, b = blockIdx.z;
    int tx = threadIdx.x, ty = threadIdx.y;
    #pragma unroll
    for (int r = ty; r < 32; r += 8)
        tile[r][tx] = qkv[(size_t)(b * SEQ + t0 + r) * QKV_COLS + 2176 + d0 + tx];
    __syncthreads();
    #pragma unroll
    for (int r = ty; r < 32; r += 8) {
        float v = tile[tx][r];
        __nv_bfloat16 h = __float2bfloat16(v);
        size_t o = ((size_t)b * HD + d0 + r) * SEQ + t0 + tx;
        vth[o] = h;
        vtl[o] = __float2bfloat16(v - __bfloat162float(h));
    }
}

// ---------------------------------------------------------------------------
extern "C" void kernel_launch(void* const* d_in, const int* in_sizes, int n_in,
                              void* d_out, int out_size) {
    const float* x      = (const float*)d_in[0];
    const float* w_attn = (const float*)d_in[1];
    const float* w_out  = (const float*)d_in[2];
    float* out = (float*)d_out;

    float *qkv;
    __nv_bfloat16 *xhi, *xlo, *wath, *watl, *woth, *wotl, *atth, *attl;
    __nv_bfloat16 *qhi, *qlo, *khi, *klo, *vth, *vtl;
    cudaGetSymbolAddress((void**)&qkv,  g_qkv);
    cudaGetSymbolAddress((void**)&xhi,  g_x_hi);
    cudaGetSymbolAddress((void**)&xlo,  g_x_lo);
    cudaGetSymbolAddress((void**)&wath, g_wat_hi);
    cudaGetSymbolAddress((void**)&watl, g_wat_lo);
    cudaGetSymbolAddress((void**)&woth, g_wot_hi);
    cudaGetSymbolAddress((void**)&wotl, g_wot_lo);
    cudaGetSymbolAddress((void**)&atth, g_att_hi);
    cudaGetSymbolAddress((void**)&attl, g_att_lo);
    cudaGetSymbolAddress((void**)&qhi,  g_q_hi);
    cudaGetSymbolAddress((void**)&qlo,  g_q_lo);
    cudaGetSymbolAddress((void**)&khi,  g_k_hi);
    cudaGetSymbolAddress((void**)&klo,  g_k_lo);
    cudaGetSymbolAddress((void**)&vth,  g_vt_hi);
    cudaGetSymbolAddress((void**)&vtl,  g_vt_lo);

    cudaFuncSetAttribute(hmma_gemm_kernel, cudaFuncAttributeMaxDynamicSharedMemorySize, GEMM_SMEM);
    cudaFuncSetAttribute(hmma_attn_kernel, cudaFuncAttributeMaxDynamicSharedMemorySize, ATT_SMEM);

    // 0) precision splits
    int nx = ROWS * NEMB;
    split_kernel<<<nx / (4 * 256), 256>>>(x, xhi, xlo, nx);
    transpose_split_kernel<<<dim3(QKV_COLS / 32, NEMB / 32), dim3(32, 8)>>>(w_attn, wath, watl, NEMB, QKV_COLS);
    transpose_split_kernel<<<dim3(NEMB / 32, NEMB / 32), dim3(32, 8)>>>(w_out, woth, wotl, NEMB, NEMB);

    // 1) qkv = x @ w_attn  (HMMA split-bf16)
    hmma_gemm_kernel<<<dim3(QKV_COLS / 128, ROWS / 128), 256, GEMM_SMEM>>>(
        xhi, xlo, wath, watl, qkv, ROWS, QKV_COLS, NEMB);

    // 2) RoPE + split q,k ; transpose + split v
    int rope_total = ROWS * 17 * 64;
    rope_split_kernel<<<(rope_total + 255) / 256, 256>>>(qkv, qhi, qlo, khi, klo);
    vt_split_kernel<<<dim3(SEQ / 32, HD / 32, BATCH), dim3(32, 8)>>>(qkv, vth, vtl);

    // 3) HMMA flash attention -> att hi/lo
    hmma_attn_kernel<<<dim3(SEQ / 128, NHEAD, BATCH), 256, ATT_SMEM>>>(
        qhi, qlo, khi, klo, vth, vtl, atth, attl);

    // 4) out = att @ w_out  (HMMA split-bf16)
    hmma_gemm_kernel<<<dim3(NEMB / 128, ROWS / 128), 256, GEMM_SMEM>>>(
        atth, attl, woth, wotl, out, ROWS, NEMB, NEMB);
}